// round 4
// baseline (speedup 1.0000x reference)
#include <cuda_runtime.h>
#include <cstdint>
#include <cstddef>

#define B_   16
#define D_   1024
#define T_   4096
#define CS_  1024
#define CD_  8
#define TPB  128
#define NBLK (B_ * T_ / TPB)              /* 512 */
#define OUT_ELEMS ((size_t)B_ * D_ * T_)  /* 67108864 */
#define IDX_OFF   OUT_ELEMS
#define LOSS_OFF  (OUT_ELEMS + (size_t)B_ * T_)

typedef unsigned long long u64;

// ---------------- device-global scratch (no allocs allowed) ----------------
__device__ __align__(16) float d_Win[D_ * CD_];   // W_in^T: [d][c]
__device__ __align__(16) float d_Cbn[CS_ * CD_];  // normalized codebook [code][c]
__device__ __align__(16) float d_Wout[D_ * CD_];  // W_out rows [d][c]
__device__ float d_rin[CD_];                      // g_in / ||v_in row||
__device__ float d_partial[NBLK];                 // per-block loss partials

// ---------------- f32x2 packed math (sm_100+) ----------------
__device__ __forceinline__ u64 pack2(float lo, float hi) {
    u64 r; asm("mov.b64 %0, {%1, %2};" : "=l"(r) : "f"(lo), "f"(hi)); return r;
}
__device__ __forceinline__ void unpack2(u64 v, float& lo, float& hi) {
    asm("mov.b64 {%0, %1}, %2;" : "=f"(lo), "=f"(hi) : "l"(v));
}
__device__ __forceinline__ u64 mul2(u64 a, u64 b) {
    u64 r; asm("mul.rn.f32x2 %0, %1, %2;" : "=l"(r) : "l"(a), "l"(b)); return r;
}
__device__ __forceinline__ void fma2(u64& d, u64 a, u64 b) {
    asm("fma.rn.f32x2 %0, %1, %2, %0;" : "+l"(d) : "l"(a), "l"(b));
}

// ---------------- prep 1: W_in row norms (tiny) ----------------
__global__ void fvq_prep1_kernel(const float* __restrict__ g_in,
                                 const float* __restrict__ v_in) {
    int w = threadIdx.x >> 5, lane = threadIdx.x & 31;
    if (w < CD_) {
        float s = 0.f;
        for (int i = lane; i < D_; i += 32) {
            float v = v_in[w * D_ + i];
            s = fmaf(v, v, s);
        }
        #pragma unroll
        for (int o = 16; o; o >>= 1) s += __shfl_xor_sync(0xffffffffu, s, o);
        if (lane == 0) d_rin[w] = g_in[w] / fmaxf(sqrtf(s), 1e-12f);
    }
}

// ---------------- prep 2: fill weight/codebook tables (64 blocks) ----------------
__global__ void fvq_prep2_kernel(const float* __restrict__ cb,
                                 const float* __restrict__ v_in,
                                 const float* __restrict__ g_out,
                                 const float* __restrict__ v_out) {
    int gid = blockIdx.x * blockDim.x + threadIdx.x;   // 0..16383

    if (gid < D_ * CD_) {                 // W_in^T fill (8192)
        int d = gid >> 3, c = gid & 7;
        d_Win[gid] = v_in[c * D_ + d] * d_rin[c];
    }
    if (gid < CS_) {                      // codebook row normalize (1024)
        float vv[8], n = 0.f;
        #pragma unroll
        for (int c = 0; c < 8; c++) { vv[c] = cb[gid * 8 + c]; n = fmaf(vv[c], vv[c], n); }
        float rn = 1.f / fmaxf(sqrtf(n), 1e-12f);
        #pragma unroll
        for (int c = 0; c < 8; c++) d_Cbn[gid * 8 + c] = vv[c] * rn;
    }
    if (gid < D_) {                       // W_out row normalize (1024)
        float vv[8], n = 0.f;
        #pragma unroll
        for (int c = 0; c < 8; c++) { vv[c] = v_out[gid * 8 + c]; n = fmaf(vv[c], vv[c], n); }
        float sc = g_out[gid] / fmaxf(sqrtf(n), 1e-12f);
        #pragma unroll
        for (int c = 0; c < 8; c++) d_Wout[gid * 8 + c] = vv[c] * sc;
    }
}

// ---------------- fused main kernel: one token per thread ----------------
__global__ void __launch_bounds__(TPB, 4)
fvq_main_kernel(const float* __restrict__ z,
                const float* __restrict__ cb,
                const float* __restrict__ b_in,
                const float* __restrict__ b_out,
                float* __restrict__ out) {
    __shared__ __align__(16) float sCbn[CS_ * CD_];   // 32 KB
    __shared__ float sLoss[TPB / 32];

    int tid = threadIdx.x;
    int b = blockIdx.x >> 5;                   // 32 blocks per batch
    int t = ((blockIdx.x & 31) << 7) + tid;    // token of this thread

    #pragma unroll
    for (int i = 0; i < (CS_ * CD_) / TPB; i++) sCbn[i * TPB + tid] = d_Cbn[i * TPB + tid];
    __syncthreads();

    // ---- Phase 1: z_e = W_in . z[b,:,t] + b_in  (accumulated in f32x2 pairs) ----
    const float* zp = z + (size_t)b * (D_ * T_) + t;
    const ulonglong2* W2 = (const ulonglong2*)d_Win;     // warp-uniform loads
    u64 ze2[4] = { pack2(b_in[0], b_in[1]), pack2(b_in[2], b_in[3]),
                   pack2(b_in[4], b_in[5]), pack2(b_in[6], b_in[7]) };
    #pragma unroll 4
    for (int d = 0; d < D_; d++) {
        float v = __ldg(zp + (size_t)d * T_);
        ulonglong2 w0 = W2[d * 2];
        ulonglong2 w1 = W2[d * 2 + 1];
        u64 v2 = pack2(v, v);
        fma2(ze2[0], w0.x, v2);
        fma2(ze2[1], w0.y, v2);
        fma2(ze2[2], w1.x, v2);
        fma2(ze2[3], w1.y, v2);
    }
    float zef[8];
    unpack2(ze2[0], zef[0], zef[1]); unpack2(ze2[1], zef[2], zef[3]);
    unpack2(ze2[2], zef[4], zef[5]); unpack2(ze2[3], zef[6], zef[7]);

    // ---- Phase 2: argmax over 1024 codes of z_e . cb_n (shared broadcast) ----
    const ulonglong2* cbn2 = (const ulonglong2*)sCbn;
    float best = __int_as_float(0xff800000);   // -inf
    int fidx = 0;
    #pragma unroll 4
    for (int cc = 0; cc < CS_; cc++) {
        ulonglong2 q0 = cbn2[cc * 2];
        ulonglong2 q1 = cbn2[cc * 2 + 1];
        u64 acc = mul2(ze2[0], q0.x);
        fma2(acc, ze2[1], q0.y);
        fma2(acc, ze2[2], q1.x);
        fma2(acc, ze2[3], q1.y);
        float lo, hi; unpack2(acc, lo, hi);
        float sc = lo + hi;
        if (sc > best) { best = sc; fidx = cc; }   // strict > keeps first max (argmax rule)
    }

    // gather raw codebook row (hot 32 KB, L1)
    const float4* cr = (const float4*)(cb + (size_t)fidx * 8);
    float4 zq0 = __ldg(cr);
    float4 zq1 = __ldg(cr + 1);

    // ---- index + commit-loss contribution ----
    out[IDX_OFF + (size_t)b * T_ + t] = (float)fidx;
    float q[8] = { zq0.x, zq0.y, zq0.z, zq0.w, zq1.x, zq1.y, zq1.z, zq1.w };
    float lsum = 0.f;
    #pragma unroll
    for (int c = 0; c < 8; c++) { float dd = zef[c] - q[c]; lsum = fmaf(dd, dd, lsum); }

    // ---- Phase 3: out[b,:,t] = W_out . z_q + b_out ----
    u64 zq2[4] = { pack2(zq0.x, zq0.y), pack2(zq0.z, zq0.w),
                   pack2(zq1.x, zq1.y), pack2(zq1.z, zq1.w) };
    const ulonglong2* Wo2 = (const ulonglong2*)d_Wout;   // warp-uniform loads
    float* op = out + (size_t)b * (D_ * T_) + t;
    #pragma unroll 4
    for (int d = 0; d < D_; d++) {
        ulonglong2 w0 = Wo2[d * 2];
        ulonglong2 w1 = Wo2[d * 2 + 1];
        u64 acc = mul2(zq2[0], w0.x);
        fma2(acc, zq2[1], w0.y);
        fma2(acc, zq2[2], w1.x);
        fma2(acc, zq2[3], w1.y);
        float lo, hi; unpack2(acc, lo, hi);
        op[(size_t)d * T_] = lo + hi + b_out[d];
    }

    // ---- deterministic block loss reduction (4 warps) ----
    #pragma unroll
    for (int o = 16; o; o >>= 1) lsum += __shfl_xor_sync(0xffffffffu, lsum, o);
    if ((tid & 31) == 0) sLoss[tid >> 5] = lsum;
    __syncthreads();
    if (tid == 0) {
        float tot = sLoss[0] + sLoss[1] + sLoss[2] + sLoss[3];
        d_partial[blockIdx.x] = tot;
    }
}

// ---------------- final: deterministic per-batch loss ----------------
__global__ void fvq_loss_kernel(float* __restrict__ out) {
    int b = threadIdx.x;
    if (b < B_) {
        float s = 0.f;
        #pragma unroll
        for (int i = 0; i < 32; i++) s += d_partial[b * 32 + i];
        out[LOSS_OFF + b] = s * (1.25f / (float)(CD_ * T_));
    }
}

extern "C" void kernel_launch(void* const* d_in, const int* in_sizes, int n_in,
                              void* d_out, int out_size) {
    (void)in_sizes; (void)n_in; (void)out_size;
    const float* z     = (const float*)d_in[0];
    const float* cb    = (const float*)d_in[1];
    const float* g_in  = (const float*)d_in[2];
    const float* v_in  = (const float*)d_in[3];
    const float* b_in  = (const float*)d_in[4];
    const float* g_out = (const float*)d_in[5];
    const float* v_out = (const float*)d_in[6];
    const float* b_out = (const float*)d_in[7];
    float* out = (float*)d_out;

    fvq_prep1_kernel<<<1, 256>>>(g_in, v_in);
    fvq_prep2_kernel<<<64, 256>>>(cb, v_in, g_out, v_out);
    fvq_main_kernel<<<NBLK, TPB>>>(z, cb, b_in, b_out, out);
    fvq_loss_kernel<<<1, 32>>>(out);
}

// round 5
// speedup vs baseline: 1.4047x; 1.4047x over previous
#include <cuda_runtime.h>
#include <cstdint>
#include <cstddef>

#define B_   16
#define D_   1024
#define T_   4096
#define CS_  1024
#define CD_  8
#define OUT_ELEMS ((size_t)B_ * D_ * T_)  /* 67108864 */
#define IDX_OFF   OUT_ELEMS
#define LOSS_OFF  (OUT_ELEMS + (size_t)B_ * T_)

#define TOK_A   32                         /* tokens per encoder block  */
#define NBLK_A  (B_ * T_ / TOK_A)          /* 2048 */
#define TOK_B   32                         /* tokens per decoder block  */
#define NBLK_B  (B_ * T_ / TOK_B)          /* 2048 */

typedef unsigned long long u64;

// ---------------- device-global scratch (no allocs allowed) ----------------
__device__ __align__(16) float d_Win[D_ * CD_];   // W_in^T: [d][c]
__device__ __align__(16) float d_Cbn[CS_ * CD_];  // normalized codebook [code][c]
__device__ __align__(16) float d_Wout[D_ * CD_];  // W_out rows [d][c]
__device__ float d_rin[CD_];                      // g_in / ||v_in row||
__device__ float d_partial[NBLK_A];               // per-block loss partials

// ---------------- f32x2 packed math (sm_100+) ----------------
__device__ __forceinline__ u64 pack2(float lo, float hi) {
    u64 r; asm("mov.b64 %0, {%1, %2};" : "=l"(r) : "f"(lo), "f"(hi)); return r;
}
__device__ __forceinline__ void unpack2(u64 v, float& lo, float& hi) {
    asm("mov.b64 {%0, %1}, %2;" : "=f"(lo), "=f"(hi) : "l"(v));
}
__device__ __forceinline__ u64 mul2(u64 a, u64 b) {
    u64 r; asm("mul.rn.f32x2 %0, %1, %2;" : "=l"(r) : "l"(a), "l"(b)); return r;
}
__device__ __forceinline__ void fma2(u64& d, u64 a, u64 b) {
    asm("fma.rn.f32x2 %0, %1, %2, %0;" : "+l"(d) : "l"(a), "l"(b));
}

// ---------------- prep 1: W_in row norms ----------------
__global__ void fvq_prep1_kernel(const float* __restrict__ g_in,
                                 const float* __restrict__ v_in) {
    int w = threadIdx.x >> 5, lane = threadIdx.x & 31;
    if (w < CD_) {
        float s = 0.f;
        for (int i = lane; i < D_; i += 32) {
            float v = v_in[w * D_ + i];
            s = fmaf(v, v, s);
        }
        #pragma unroll
        for (int o = 16; o; o >>= 1) s += __shfl_xor_sync(0xffffffffu, s, o);
        if (lane == 0) d_rin[w] = g_in[w] / fmaxf(sqrtf(s), 1e-12f);
    }
}

// ---------------- prep 2: fill weight/codebook tables ----------------
__global__ void fvq_prep2_kernel(const float* __restrict__ cb,
                                 const float* __restrict__ v_in,
                                 const float* __restrict__ g_out,
                                 const float* __restrict__ v_out) {
    int gid = blockIdx.x * blockDim.x + threadIdx.x;   // 0..16383

    if (gid < D_ * CD_) {                 // W_in^T fill (8192)
        int d = gid >> 3, c = gid & 7;
        d_Win[gid] = v_in[c * D_ + d] * d_rin[c];
    }
    if (gid < CS_) {                      // codebook row normalize (1024)
        float vv[8], n = 0.f;
        #pragma unroll
        for (int c = 0; c < 8; c++) { vv[c] = cb[gid * 8 + c]; n = fmaf(vv[c], vv[c], n); }
        float rn = 1.f / fmaxf(sqrtf(n), 1e-12f);
        #pragma unroll
        for (int c = 0; c < 8; c++) d_Cbn[gid * 8 + c] = vv[c] * rn;
    }
    if (gid < D_) {                       // W_out row normalize (1024)
        float vv[8], n = 0.f;
        #pragma unroll
        for (int c = 0; c < 8; c++) { vv[c] = v_out[gid * 8 + c]; n = fmaf(vv[c], vv[c], n); }
        float sc = g_out[gid] / fmaxf(sqrtf(n), 1e-12f);
        #pragma unroll
        for (int c = 0; c < 8; c++) d_Wout[gid * 8 + c] = vv[c] * sc;
    }
}

// ---------------- encoder: z_e + argmax + idx + loss ----------------
// Block = 256 threads = 32 tokens (j = tid&31) x 8 D-slices (s = tid>>5).
__global__ void __launch_bounds__(256)
fvq_enc_kernel(const float* __restrict__ z,
               const float* __restrict__ cb,
               const float* __restrict__ b_in,
               float* __restrict__ out) {
    __shared__ __align__(16) float4 sZe[8][TOK_A * 2];  // [slice][token*2] -> 8 KB
    __shared__ float2 sArg[8][TOK_A];                   // 2 KB

    int tid = threadIdx.x;
    int j = tid & 31;                    // token within tile
    int s = tid >> 5;                    // slice 0..7 (= warp id)
    int b = blockIdx.x >> 7;             // 128 blocks per batch
    int t = ((blockIdx.x & 127) << 5) + j;

    // ---- Phase 1: partial z_e over this slice's 128 D-rows ----
    const float* zp = z + ((size_t)b * D_ + s * 128) * T_ + t;
    const ulonglong2* W2 = (const ulonglong2*)d_Win + (size_t)(s * 128) * 2;
    u64 ze2[4] = {0ull, 0ull, 0ull, 0ull};
    #pragma unroll 8
    for (int d = 0; d < 128; d++) {
        float v = __ldg(zp + (size_t)d * T_);
        ulonglong2 w0 = W2[d * 2];
        ulonglong2 w1 = W2[d * 2 + 1];
        u64 v2 = pack2(v, v);
        fma2(ze2[0], w0.x, v2);
        fma2(ze2[1], w0.y, v2);
        fma2(ze2[2], w1.x, v2);
        fma2(ze2[3], w1.y, v2);
    }
    {
        float p0, p1, p2, p3, p4, p5, p6, p7;
        unpack2(ze2[0], p0, p1); unpack2(ze2[1], p2, p3);
        unpack2(ze2[2], p4, p5); unpack2(ze2[3], p6, p7);
        sZe[s][j * 2 + 0] = make_float4(p0, p1, p2, p3);
        sZe[s][j * 2 + 1] = make_float4(p4, p5, p6, p7);
    }
    __syncthreads();

    // every thread of token j rebuilds the full z_e (needed for its argmax slice)
    float zef[8];
    #pragma unroll
    for (int c = 0; c < 8; c++) zef[c] = b_in[c];
    #pragma unroll
    for (int s2 = 0; s2 < 8; s2++) {
        float4 a = sZe[s2][j * 2 + 0];
        float4 c4 = sZe[s2][j * 2 + 1];
        zef[0] += a.x;  zef[1] += a.y;  zef[2] += a.z;  zef[3] += a.w;
        zef[4] += c4.x; zef[5] += c4.y; zef[6] += c4.z; zef[7] += c4.w;
    }

    // ---- Phase 2: argmax over this slice's 128 codes (warp-uniform L1 loads) ----
    u64 zp2[4] = { pack2(zef[0], zef[1]), pack2(zef[2], zef[3]),
                   pack2(zef[4], zef[5]), pack2(zef[6], zef[7]) };
    const ulonglong2* cbn2 = (const ulonglong2*)d_Cbn + (size_t)(s * 128) * 2;
    float best = __int_as_float(0xff800000);  // -inf
    int bidx = 0;
    #pragma unroll 4
    for (int cc = 0; cc < 128; cc++) {
        ulonglong2 q0 = cbn2[cc * 2];
        ulonglong2 q1 = cbn2[cc * 2 + 1];
        u64 acc = mul2(zp2[0], q0.x);
        fma2(acc, zp2[1], q0.y);
        fma2(acc, zp2[2], q1.x);
        fma2(acc, zp2[3], q1.y);
        float lo, hi; unpack2(acc, lo, hi);
        float sc = lo + hi;
        if (sc > best) { best = sc; bidx = cc; }  // ascending -> first max wins
    }
    sArg[s][j] = make_float2(best, __int_as_float(s * 128 + bidx));
    __syncthreads();

    // ---- slice 0 threads (warp 0) finalize their token ----
    if (s == 0) {
        float fbest = __int_as_float(0xff800000);
        int fidx = 0;
        #pragma unroll
        for (int s2 = 0; s2 < 8; s2++) {   // ascending slice order preserves first-max rule
            float2 cnd = sArg[s2][j];
            if (cnd.x > fbest) { fbest = cnd.x; fidx = __float_as_int(cnd.y); }
        }
        out[IDX_OFF + (size_t)b * T_ + t] = (float)fidx;

        const float4* cr = (const float4*)(cb + (size_t)fidx * 8);
        float4 zq0 = __ldg(cr);
        float4 zq1 = __ldg(cr + 1);
        float q[8] = { zq0.x, zq0.y, zq0.z, zq0.w, zq1.x, zq1.y, zq1.z, zq1.w };
        float lsum = 0.f;
        #pragma unroll
        for (int c = 0; c < 8; c++) { float dd = zef[c] - q[c]; lsum = fmaf(dd, dd, lsum); }
        #pragma unroll
        for (int o = 16; o; o >>= 1) lsum += __shfl_xor_sync(0xffffffffu, lsum, o);
        if (j == 0) d_partial[blockIdx.x] = lsum;
    }
}

// ---------------- decoder: out = W_out . z_q + b_out (+ loss finalize) ----------------
// Block = 256 threads = 8 warps x 32 tokens. Warp w covers d rows [w*128, (w+1)*128).
__global__ void __launch_bounds__(256)
fvq_dec_kernel(const float* __restrict__ cb,
               const float* __restrict__ b_out,
               float* __restrict__ out) {
    int tid = threadIdx.x;
    int lane = tid & 31;
    int w = tid >> 5;                    // warp id 0..7
    int b = blockIdx.x >> 7;             // 128 blocks per batch
    int t = ((blockIdx.x & 127) << 5) + lane;

    // loss finalization piggybacks on the first 16 blocks (A's partials are visible)
    if (blockIdx.x < B_ && tid == 0) {
        float sum = 0.f;
        #pragma unroll 8
        for (int i = 0; i < 128; i++) sum += d_partial[blockIdx.x * 128 + i];
        out[LOSS_OFF + blockIdx.x] = sum * (1.25f / (float)(CD_ * T_));
    }

    int fidx = (int)out[IDX_OFF + (size_t)b * T_ + t];
    const float4* cr = (const float4*)(cb + (size_t)fidx * 8);
    float4 zq0 = __ldg(cr);
    float4 zq1 = __ldg(cr + 1);
    u64 zq2[4] = { pack2(zq0.x, zq0.y), pack2(zq0.z, zq0.w),
                   pack2(zq1.x, zq1.y), pack2(zq1.z, zq1.w) };

    const ulonglong2* Wo2 = (const ulonglong2*)d_Wout + (size_t)(w * 128) * 2;
    const float* bo = b_out + w * 128;
    float* op = out + ((size_t)b * D_ + w * 128) * T_ + t;
    #pragma unroll 8
    for (int d = 0; d < 128; d++) {
        ulonglong2 w0 = Wo2[d * 2];          // warp-uniform
        ulonglong2 w1 = Wo2[d * 2 + 1];
        u64 acc = mul2(zq2[0], w0.x);
        fma2(acc, zq2[1], w0.y);
        fma2(acc, zq2[2], w1.x);
        fma2(acc, zq2[3], w1.y);
        float lo, hi; unpack2(acc, lo, hi);
        op[(size_t)d * T_] = lo + hi + bo[d];
    }
}

extern "C" void kernel_launch(void* const* d_in, const int* in_sizes, int n_in,
                              void* d_out, int out_size) {
    (void)in_sizes; (void)n_in; (void)out_size;
    const float* z     = (const float*)d_in[0];
    const float* cb    = (const float*)d_in[1];
    const float* g_in  = (const float*)d_in[2];
    const float* v_in  = (const float*)d_in[3];
    const float* b_in  = (const float*)d_in[4];
    const float* g_out = (const float*)d_in[5];
    const float* v_out = (const float*)d_in[6];
    const float* b_out = (const float*)d_in[7];
    float* out = (float*)d_out;

    fvq_prep1_kernel<<<1, 256>>>(g_in, v_in);
    fvq_prep2_kernel<<<64, 256>>>(cb, v_in, g_out, v_out);
    fvq_enc_kernel<<<NBLK_A, 256>>>(z, cb, b_in, out);
    fvq_dec_kernel<<<NBLK_B, 256>>>(cb, b_out, out);
}

// round 6
// speedup vs baseline: 2.0405x; 1.4527x over previous
#include <cuda_runtime.h>
#include <cstdint>
#include <cstddef>

#define B_   16
#define D_   1024
#define T_   4096
#define CS_  1024
#define CD_  8
#define OUT_ELEMS ((size_t)B_ * D_ * T_)  /* 67108864 */
#define IDX_OFF   OUT_ELEMS
#define LOSS_OFF  (OUT_ELEMS + (size_t)B_ * T_)

#define NBLK_E  1024     /* encoder: 64 tokens per block  */
#define NBLK_D  512      /* decoder: 128 tokens per block */

typedef unsigned long long u64;

// ---------------- device-global scratch (no allocs allowed) ----------------
__device__ __align__(16) float d_Win[D_ * CD_];   // W_in^T: [d][c]
__device__ __align__(16) float d_Cbn[CS_ * CD_];  // normalized codebook [code][c]
__device__ __align__(16) float d_Wout[D_ * CD_];  // W_out rows [d][c]
__device__ float d_partial[NBLK_E];               // per-encoder-block loss partials

// ---------------- f32x2 packed math (sm_100+) ----------------
__device__ __forceinline__ u64 pack2(float lo, float hi) {
    u64 r; asm("mov.b64 %0, {%1, %2};" : "=l"(r) : "f"(lo), "f"(hi)); return r;
}
__device__ __forceinline__ void unpack2(u64 v, float& lo, float& hi) {
    asm("mov.b64 {%0, %1}, %2;" : "=f"(lo), "=f"(hi) : "l"(v));
}
__device__ __forceinline__ u64 mul2(u64 a, u64 b) {
    u64 r; asm("mul.rn.f32x2 %0, %1, %2;" : "=l"(r) : "l"(a), "l"(b)); return r;
}
__device__ __forceinline__ void fma2(u64& d, u64 a, u64 b) {
    asm("fma.rn.f32x2 %0, %1, %2, %0;" : "+l"(d) : "l"(a), "l"(b));
}

// ---------------- single prep kernel (16 blocks) ----------------
// blocks 0..7:  W_in^T fill (block = c, warp = 128-d segment; warp recomputes row norm)
// blocks 8..11: codebook normalize
// blocks 12..15: W_out normalize
__global__ void fvq_prep_kernel(const float* __restrict__ cb,
                                const float* __restrict__ g_in,
                                const float* __restrict__ v_in,
                                const float* __restrict__ g_out,
                                const float* __restrict__ v_out) {
    int tid = threadIdx.x, lane = tid & 31, w = tid >> 5;
    int blk = blockIdx.x;

    if (blk < 8) {                       // W_in^T fill for c = blk
        int c = blk;
        const float4* v4 = (const float4*)(v_in + c * D_);
        float s = 0.f;
        #pragma unroll
        for (int k = 0; k < 8; k++) {
            float4 a = __ldg(v4 + k * 32 + lane);
            s = fmaf(a.x, a.x, s); s = fmaf(a.y, a.y, s);
            s = fmaf(a.z, a.z, s); s = fmaf(a.w, a.w, s);
        }
        #pragma unroll
        for (int o = 16; o; o >>= 1) s += __shfl_xor_sync(0xffffffffu, s, o);
        float rsc = __ldg(g_in + c) / fmaxf(sqrtf(__shfl_sync(0xffffffffu, s, 0)), 1e-12f);
        #pragma unroll
        for (int k = 0; k < 4; k++) {
            int d = w * 128 + k * 32 + lane;
            d_Win[d * 8 + c] = v_in[c * D_ + d] * rsc;
        }
    } else if (blk < 12) {               // codebook rows
        int r = (blk - 8) * 256 + tid;
        float vv[8], n = 0.f;
        #pragma unroll
        for (int c = 0; c < 8; c++) { vv[c] = cb[r * 8 + c]; n = fmaf(vv[c], vv[c], n); }
        float rn = 1.f / fmaxf(sqrtf(n), 1e-12f);
        #pragma unroll
        for (int c = 0; c < 8; c++) d_Cbn[r * 8 + c] = vv[c] * rn;
    } else {                              // W_out rows
        int r = (blk - 12) * 256 + tid;
        float vv[8], n = 0.f;
        #pragma unroll
        for (int c = 0; c < 8; c++) { vv[c] = v_out[r * 8 + c]; n = fmaf(vv[c], vv[c], n); }
        float sc = g_out[r] / fmaxf(sqrtf(n), 1e-12f);
        #pragma unroll
        for (int c = 0; c < 8; c++) d_Wout[r * 8 + c] = vv[c] * sc;
    }
}

// ---------------- encoder: z_e + argmax + idx + loss ----------------
// Block = 256 threads = 32 token-pairs (j) x 8 slices (s). 64 tokens/block.
__global__ void __launch_bounds__(256)
fvq_enc_kernel(const float* __restrict__ z,
               const float* __restrict__ cb,
               const float* __restrict__ b_in,
               float* __restrict__ out) {
    __shared__ __align__(16) float4 sZe[8][64 * 2];   // 16 KB: [slice][token*2]
    __shared__ float2 sArg[8][64];                    //  4 KB

    int tid = threadIdx.x;
    int j = tid & 31;                    // token-pair id
    int s = tid >> 5;                    // slice 0..7 (= warp id)
    int b = blockIdx.x >> 6;             // 64 blocks per batch
    int t0 = ((blockIdx.x & 63) << 6) + j * 2;

    // ---- Phase 1: partial z_e over this slice's 128 D-rows, 2 tokens ----
    const float* zp = z + ((size_t)b * D_ + s * 128) * T_ + t0;
    const ulonglong2* W2 = (const ulonglong2*)d_Win + (size_t)(s * 128) * 2;
    u64 zeA[4] = {0ull,0ull,0ull,0ull}, zeB[4] = {0ull,0ull,0ull,0ull};
    #pragma unroll 8
    for (int d = 0; d < 128; d++) {
        float2 v = __ldg((const float2*)(zp + (size_t)d * T_));
        ulonglong2 w0 = W2[d * 2];
        ulonglong2 w1 = W2[d * 2 + 1];
        u64 vA = pack2(v.x, v.x), vB = pack2(v.y, v.y);
        fma2(zeA[0], w0.x, vA); fma2(zeB[0], w0.x, vB);
        fma2(zeA[1], w0.y, vA); fma2(zeB[1], w0.y, vB);
        fma2(zeA[2], w1.x, vA); fma2(zeB[2], w1.x, vB);
        fma2(zeA[3], w1.y, vA); fma2(zeB[3], w1.y, vB);
    }
    {
        float p0,p1,p2,p3,p4,p5,p6,p7;
        unpack2(zeA[0],p0,p1); unpack2(zeA[1],p2,p3); unpack2(zeA[2],p4,p5); unpack2(zeA[3],p6,p7);
        sZe[s][(j*2+0)*2+0] = make_float4(p0,p1,p2,p3);
        sZe[s][(j*2+0)*2+1] = make_float4(p4,p5,p6,p7);
        unpack2(zeB[0],p0,p1); unpack2(zeB[1],p2,p3); unpack2(zeB[2],p4,p5); unpack2(zeB[3],p6,p7);
        sZe[s][(j*2+1)*2+0] = make_float4(p0,p1,p2,p3);
        sZe[s][(j*2+1)*2+1] = make_float4(p4,p5,p6,p7);
    }
    __syncthreads();

    // rebuild full z_e for both tokens
    float zefA[8], zefB[8];
    #pragma unroll
    for (int c = 0; c < 8; c++) { zefA[c] = b_in[c]; zefB[c] = b_in[c]; }
    #pragma unroll
    for (int s2 = 0; s2 < 8; s2++) {
        float4 a0 = sZe[s2][(j*2+0)*2+0], a1 = sZe[s2][(j*2+0)*2+1];
        float4 b0 = sZe[s2][(j*2+1)*2+0], b1 = sZe[s2][(j*2+1)*2+1];
        zefA[0]+=a0.x; zefA[1]+=a0.y; zefA[2]+=a0.z; zefA[3]+=a0.w;
        zefA[4]+=a1.x; zefA[5]+=a1.y; zefA[6]+=a1.z; zefA[7]+=a1.w;
        zefB[0]+=b0.x; zefB[1]+=b0.y; zefB[2]+=b0.z; zefB[3]+=b0.w;
        zefB[4]+=b1.x; zefB[5]+=b1.y; zefB[6]+=b1.z; zefB[7]+=b1.w;
    }

    // ---- Phase 2: argmax over this slice's 128 codes, both tokens share loads ----
    u64 zA2[4] = { pack2(zefA[0],zefA[1]), pack2(zefA[2],zefA[3]),
                   pack2(zefA[4],zefA[5]), pack2(zefA[6],zefA[7]) };
    u64 zB2[4] = { pack2(zefB[0],zefB[1]), pack2(zefB[2],zefB[3]),
                   pack2(zefB[4],zefB[5]), pack2(zefB[6],zefB[7]) };
    const ulonglong2* cbn2 = (const ulonglong2*)d_Cbn + (size_t)(s * 128) * 2;
    float bestA = __int_as_float(0xff800000), bestB = bestA;
    int idxA = 0, idxB = 0;
    #pragma unroll 4
    for (int cc = 0; cc < 128; cc++) {
        ulonglong2 q0 = cbn2[cc * 2];
        ulonglong2 q1 = cbn2[cc * 2 + 1];
        u64 aA = mul2(zA2[0], q0.x); u64 aB = mul2(zB2[0], q0.x);
        fma2(aA, zA2[1], q0.y);      fma2(aB, zB2[1], q0.y);
        fma2(aA, zA2[2], q1.x);      fma2(aB, zB2[2], q1.x);
        fma2(aA, zA2[3], q1.y);      fma2(aB, zB2[3], q1.y);
        float lo, hi;
        unpack2(aA, lo, hi); float scA = lo + hi;
        unpack2(aB, lo, hi); float scB = lo + hi;
        if (scA > bestA) { bestA = scA; idxA = cc; }
        if (scB > bestB) { bestB = scB; idxB = cc; }
    }
    sArg[s][j*2+0] = make_float2(bestA, __int_as_float(s * 128 + idxA));
    sArg[s][j*2+1] = make_float2(bestB, __int_as_float(s * 128 + idxB));
    __syncthreads();

    // ---- warp 0 finalizes: each thread owns its 2 tokens ----
    if (s == 0) {
        float lsum = 0.f;
        #pragma unroll
        for (int u = 0; u < 2; u++) {
            float fbest = __int_as_float(0xff800000);
            int fidx = 0;
            #pragma unroll
            for (int s2 = 0; s2 < 8; s2++) {   // ascending code order -> first max wins
                float2 cnd = sArg[s2][j*2+u];
                if (cnd.x > fbest) { fbest = cnd.x; fidx = __float_as_int(cnd.y); }
            }
            out[IDX_OFF + (size_t)b * T_ + t0 + u] = (float)fidx;
            const float4* cr = (const float4*)(cb + (size_t)fidx * 8);
            float4 zq0 = __ldg(cr);
            float4 zq1 = __ldg(cr + 1);
            const float* zef = u ? zefB : zefA;
            float q[8] = { zq0.x,zq0.y,zq0.z,zq0.w, zq1.x,zq1.y,zq1.z,zq1.w };
            #pragma unroll
            for (int c = 0; c < 8; c++) { float dd = zef[c] - q[c]; lsum = fmaf(dd, dd, lsum); }
        }
        #pragma unroll
        for (int o = 16; o; o >>= 1) lsum += __shfl_xor_sync(0xffffffffu, lsum, o);
        if (j == 0) d_partial[blockIdx.x] = lsum;
    }
}

// ---------------- decoder: out = W_out . z_q + b_out (+ loss finalize) ----------------
// Block = 256 threads = 8 warps (d-slices of 128) x 32 lanes (4 tokens each). 128 tokens/block.
__global__ void __launch_bounds__(256)
fvq_dec_kernel(const float* __restrict__ cb,
               const float* __restrict__ b_out,
               float* __restrict__ out) {
    int tid = threadIdx.x;
    int lane = tid & 31;
    int w = tid >> 5;                    // warp id -> d rows [w*128, w*128+128)
    int b = blockIdx.x >> 5;             // 32 blocks per batch
    int t0 = ((blockIdx.x & 31) << 7) + lane * 4;

    // loss finalization (first 16 blocks; encoder partials are visible)
    if (blockIdx.x < B_ && tid == 0) {
        float sum = 0.f;
        #pragma unroll 8
        for (int i = 0; i < 64; i++) sum += d_partial[blockIdx.x * 64 + i];
        out[LOSS_OFF + blockIdx.x] = sum * (1.25f / (float)(CD_ * T_));
    }

    // 4 token indices (vector load) + 4 codebook gathers
    float4 idx4 = *(const float4*)(out + IDX_OFF + (size_t)b * T_ + t0);
    u64 zq2[4][4];
    #pragma unroll
    for (int k = 0; k < 4; k++) {
        int fidx = (int)((&idx4.x)[k]);
        const float4* cr = (const float4*)(cb + (size_t)fidx * 8);
        float4 zq0 = __ldg(cr);
        float4 zq1 = __ldg(cr + 1);
        zq2[k][0] = pack2(zq0.x, zq0.y); zq2[k][1] = pack2(zq0.z, zq0.w);
        zq2[k][2] = pack2(zq1.x, zq1.y); zq2[k][3] = pack2(zq1.z, zq1.w);
    }

    const ulonglong2* Wo2 = (const ulonglong2*)d_Wout + (size_t)(w * 128) * 2;
    const float* bo = b_out + w * 128;
    float* op = out + ((size_t)b * D_ + w * 128) * T_ + t0;
    #pragma unroll 4
    for (int d = 0; d < 128; d++) {
        ulonglong2 w0 = Wo2[d * 2];          // warp-uniform
        ulonglong2 w1 = Wo2[d * 2 + 1];
        float bias = bo[d];
        float4 o4;
        #pragma unroll
        for (int k = 0; k < 4; k++) {
            u64 acc = mul2(zq2[k][0], w0.x);
            fma2(acc, zq2[k][1], w0.y);
            fma2(acc, zq2[k][2], w1.x);
            fma2(acc, zq2[k][3], w1.y);
            float lo, hi; unpack2(acc, lo, hi);
            (&o4.x)[k] = lo + hi + bias;
        }
        *(float4*)(op + (size_t)d * T_) = o4;
    }
}

extern "C" void kernel_launch(void* const* d_in, const int* in_sizes, int n_in,
                              void* d_out, int out_size) {
    (void)in_sizes; (void)n_in; (void)out_size;
    const float* z     = (const float*)d_in[0];
    const float* cb    = (const float*)d_in[1];
    const float* g_in  = (const float*)d_in[2];
    const float* v_in  = (const float*)d_in[3];
    const float* b_in  = (const float*)d_in[4];
    const float* g_out = (const float*)d_in[5];
    const float* v_out = (const float*)d_in[6];
    const float* b_out = (const float*)d_in[7];
    float* out = (float*)d_out;

    fvq_prep_kernel<<<16, 256>>>(cb, g_in, v_in, g_out, v_out);
    fvq_enc_kernel<<<NBLK_E, 256>>>(z, cb, b_in, out);
    fvq_dec_kernel<<<NBLK_D, 256>>>(cb, b_out, out);
}